// round 11
// baseline (speedup 1.0000x reference)
#include <cuda_runtime.h>
#include <math.h>
#include <stdint.h>

#define Nn 8192
#define IN_FEAT 128
#define OUTF 64
#define LALPHA 0.2f
#define NEG_BIG (-9e15f)

#define BI 32              // rows per tile
#define BJ 64              // j-chunk
#define JS 2               // j-split CTAs per tile
#define NCH ((Nn/JS)/BJ)   // 64 chunks per CTA
#define TPB 256
#define HST 72             // hs stride; 72 % 32 == 8 -> B-frag LDS conflict-free
#define PST 68             // ps stride; 68 % 32 == 4 -> A-frag LDS conflict-free
#define SMEM_BYTES ((2*BJ*HST + 2*BI*PST)*4)   // 54272 B -> 3 CTAs/SM

// Scratch (device globals — no allocation allowed)
__device__ float g_htf[Nn*OUTF];               // h pre-rounded to tf32
__device__ float g_si[Nn];
__device__ float g_sj[Nn];
__device__ unsigned g_sjmax_enc;               // order-preserving encoding
__device__ float g_pacc[(Nn/BI)*JS*BI*OUTF];   // partial P@H per split CTA
__device__ float g_pl[(Nn/BI)*JS*BI];          // partial row sums

__device__ __forceinline__ uint32_t f2tf(float x) {
    uint32_t r;
    asm("cvt.rna.tf32.f32 %0, %1;" : "=r"(r) : "f"(x));
    return r;
}
__device__ __forceinline__ unsigned enc_f(float x) {
    unsigned u = __float_as_uint(x);
    return (u & 0x80000000u) ? ~u : (u | 0x80000000u);
}
__device__ __forceinline__ float dec_f(unsigned u) {
    return __uint_as_float((u & 0x80000000u) ? (u & 0x7FFFFFFFu) : ~u);
}
__device__ __forceinline__ void mma_tf32(float* c,
                                         uint32_t a0, uint32_t a1, uint32_t a2, uint32_t a3,
                                         uint32_t b0, uint32_t b1) {
    asm volatile(
        "mma.sync.aligned.m16n8k8.row.col.f32.tf32.tf32.f32 "
        "{%0,%1,%2,%3}, {%4,%5,%6,%7}, {%8,%9}, {%0,%1,%2,%3};"
        : "+f"(c[0]), "+f"(c[1]), "+f"(c[2]), "+f"(c[3])
        : "r"(a0), "r"(a1), "r"(a2), "r"(a3), "r"(b0), "r"(b1));
}

// ---------------------------------------------------------------------------
// K1: h = features @ W.T (tf32-rounded) + s_i/s_j + max(s_j).
// Re-tiled: 16 rows/CTA, grid 512 (3.46 CTAs/SM), 16 threads/row x 4 outputs.
// ---------------------------------------------------------------------------
__global__ void __launch_bounds__(256) k_h(const float* __restrict__ feat,
                                           const float* __restrict__ W,
                                           const float* __restrict__ avec) {
    __shared__ float Wt[IN_FEAT][OUTF];
    __shared__ float sjred[16];
    int t = threadIdx.x;
#pragma unroll
    for (int w = 0; w < 8; w++) {
        int idx = t + 256 * w;
        int f   = idx >> 5;
        int c4  = idx & 31;
        float4 wv = ((const float4*)W)[idx];
        int k = c4 * 4;
        Wt[k + 0][f] = wv.x;
        Wt[k + 1][f] = wv.y;
        Wt[k + 2][f] = wv.z;
        Wt[k + 3][f] = wv.w;
    }
    __syncthreads();

    int il = t >> 4;                    // row 0..15
    int fo = t & 15;                    // 4 output cols per thread
    int i  = blockIdx.x * 16 + il;
    const float4* fr = (const float4*)(feat + (size_t)i * IN_FEAT);

    float acc[4];
#pragma unroll
    for (int c = 0; c < 4; c++) acc[c] = 0.f;

#pragma unroll
    for (int kk = 0; kk < 32; kk++) {
        float4 fv = fr[kk];
#pragma unroll
        for (int c = 0; c < 4; c++) {
            float fc = (c == 0) ? fv.x : (c == 1) ? fv.y : (c == 2) ? fv.z : fv.w;
            int k = kk * 4 + c;
            float4 w0 = *(const float4*)&Wt[k][fo * 4];
            acc[0] += fc * w0.x; acc[1] += fc * w0.y;
            acc[2] += fc * w0.z; acc[3] += fc * w0.w;
        }
    }
    uint4 o0;
    o0.x = f2tf(acc[0]); o0.y = f2tf(acc[1]); o0.z = f2tf(acc[2]); o0.w = f2tf(acc[3]);
    *(uint4*)(g_htf + (size_t)i * OUTF + fo * 4) = o0;

    float sx = 0.f, sy = 0.f;
#pragma unroll
    for (int c = 0; c < 4; c++) {
        sx += acc[c] * avec[fo * 4 + c];
        sy += acc[c] * avec[OUTF + fo * 4 + c];
    }
#pragma unroll
    for (int o = 8; o > 0; o >>= 1) {
        sx += __shfl_down_sync(0xffffffffu, sx, o, 16);
        sy += __shfl_down_sync(0xffffffffu, sy, o, 16);
    }
    if (fo == 0) {
        g_si[i] = sx;
        g_sj[i] = sy;
        sjred[il] = sy;
    }
    __syncthreads();
    if (t == 0) {
        float m = sjred[0];
#pragma unroll
        for (int c = 1; c < 16; c++) m = fmaxf(m, sjred[c]);
        atomicMax(&g_sjmax_enc, enc_f(m));   // idempotent across replays
    }
}

// ---------------------------------------------------------------------------
// K2: R10 structure with ps double-buffered -> ONE sync per chunk.
// 54.3 KB smem, 3 CTAs/SM, grid 512.
// ---------------------------------------------------------------------------
__global__ void __launch_bounds__(TPB, 3) k_main(const float* __restrict__ geo,
                                                 const float* __restrict__ sem) {
    extern __shared__ float smem[];
    float* hsb[2] = { smem, smem + BJ * HST };
    float* psb[2] = { smem + 2 * BJ * HST, smem + 2 * BJ * HST + BI * PST };

    int t     = threadIdx.x;
    int bid   = blockIdx.x;
    int tile  = bid >> 1;
    int half  = bid & 1;
    int i0    = tile * BI;
    int jbase = half * (Nn / JS);
    int lane  = t & 31;
    int warp  = t >> 5;

    // ---- score mapping: 8 threads/row ----
    int r = t >> 3;
    int q = t & 7;
    float si_r  = g_si[i0 + r];
    float m_r   = fmaxf(0.f, 2.f * (si_r + dec_f(g_sjmax_enc)));
    float l_acc = 0.f;
    const float4* gbase = (const float4*)(geo + (size_t)(i0 + r) * Nn + jbase);
    const float4* sbase = (const float4*)(sem + (size_t)(i0 + r) * Nn + jbase);
    const float4* sjb   = (const float4*)(g_sj + jbase);

    // ---- staging mapping ----
    int jr = t >> 4, f4 = t & 15;

    // ---- gemm mapping: 8 warps = 2(m) x 4(n), warp tile m16 x n16 ----
    int wm = warp & 1, wn = warp >> 1;
    int m0 = wm * 16, n0 = wn * 16;
    int ar = lane >> 2, ac = lane & 3;
    int bk = lane & 3,  bn = lane >> 2;

    float acc[2][4];
#pragma unroll
    for (int a = 0; a < 2; a++)
#pragma unroll
        for (int b = 0; b < 4; b++) acc[a][b] = 0.f;

    // prefetch adjacency chunk 0
    float4 gv[2], sv[2];
#pragma unroll
    for (int kk = 0; kk < 2; kk++) {
        gv[kk] = __ldcs(&gbase[q + 8 * kk]);
        sv[kk] = __ldcs(&sbase[q + 8 * kk]);
    }

    int buf = 0;
    for (int ci = 0; ci < NCH; ci++, buf ^= 1) {
        float* hs = hsb[buf];
        float* ps = psb[buf];

        // ---- stage h chunk into hs[buf] ----
        int jrow = jbase + ci * BJ;
#pragma unroll
        for (int it = 0; it < 4; it++) {
            int j = jr + 16 * it;
            float4 hv = *(const float4*)(g_htf + (size_t)(jrow + j) * OUTF + f4 * 4);
            *(float4*)(hs + j * HST + f4 * 4) = hv;
        }

        // ---- scores -> ps[buf] ----
        int cb4 = ci * (BJ / 4);
#pragma unroll
        for (int kk = 0; kk < 2; kk++) {
            int f4i = q + 8 * kk;
            int j0l = f4i * 4;
            float4 g4 = gv[kk], s4 = sv[kk];
            float4 sj4 = __ldg(&sjb[cb4 + f4i]);
            uint4 po;
            uint32_t* pd = (uint32_t*)&po;
#pragma unroll
            for (int c = 0; c < 4; c++) {
                float g = (c == 0) ? g4.x : (c == 1) ? g4.y : (c == 2) ? g4.z : g4.w;
                float s = (c == 0) ? s4.x : (c == 1) ? s4.y : (c == 2) ? s4.z : s4.w;
                float sj = (c == 0) ? sj4.x : (c == 1) ? sj4.y : (c == 2) ? sj4.z : sj4.w;
                float cmb = g + s;
                float x = si_r + sj;
                x = (x > 0.f) ? x : LALPHA * x;
                float val = (cmb > 0.f) ? x * cmb : NEG_BIG;
                float p = __expf(val - m_r);
                l_acc += p;
                pd[c] = f2tf(p);
            }
            *(uint4*)(ps + r * PST + j0l) = po;
        }

        // ---- prefetch next adjacency chunk ----
        int cn4 = (ci + 1 < NCH) ? (ci + 1) * (BJ / 4) : 0;
#pragma unroll
        for (int kk = 0; kk < 2; kk++) {
            gv[kk] = __ldcs(&gbase[cn4 + q + 8 * kk]);
            sv[kk] = __ldcs(&sbase[cn4 + q + 8 * kk]);
        }

        __syncthreads();   // single barrier: writes(ci) -> reads(ci)

        // ---- tensor-core GEMM: acc += P[32,64] @ H[64,64] ----
        const float* psA = ps + (m0 + ar) * PST + ac;
        const float* hsB = hs + bk * HST + n0 + bn;
#pragma unroll
        for (int ks = 0; ks < 8; ks++) {
            int k0 = ks * 8;
            uint32_t a0 = __float_as_uint(psA[k0]);
            uint32_t a1 = __float_as_uint(psA[8 * PST + k0]);
            uint32_t a2 = __float_as_uint(psA[k0 + 4]);
            uint32_t a3 = __float_as_uint(psA[8 * PST + k0 + 4]);
#pragma unroll
            for (int nt = 0; nt < 2; nt++) {
                uint32_t b0 = __float_as_uint(hsB[k0 * HST + nt * 8]);
                uint32_t b1 = __float_as_uint(hsB[(k0 + 4) * HST + nt * 8]);
                mma_tf32(acc[nt], a0, a1, a2, a3, b0, b1);
            }
        }
        // next iteration writes buf^1 -> no race with this GEMM's readers
    }

    // ---- partial l: reduce across the 8 threads of each row ----
#pragma unroll
    for (int o = 4; o > 0; o >>= 1)
        l_acc += __shfl_down_sync(0xffffffffu, l_acc, o, 8);
    if (q == 0) g_pl[(size_t)bid * BI + r] = l_acc;

    // ---- partial acc -> global (unnormalized; exact since m_r is global) ----
    float* pout = g_pacc + (size_t)bid * BI * OUTF;
    int row0 = m0 + (lane >> 2);
    int col0 = 2 * (lane & 3);
#pragma unroll
    for (int nt = 0; nt < 2; nt++) {
        int col = n0 + nt * 8 + col0;
        *(float2*)(pout + row0 * OUTF + col)       = make_float2(acc[nt][0], acc[nt][1]);
        *(float2*)(pout + (row0 + 8) * OUTF + col) = make_float2(acc[nt][2], acc[nt][3]);
    }
}

// ---------------------------------------------------------------------------
// K3: combine j-split partials, normalize, ELU
// ---------------------------------------------------------------------------
__global__ void __launch_bounds__(256) k_fin(float* __restrict__ out) {
    int t = threadIdx.x;
    int i = blockIdx.x * 64 + (t >> 2);
    int f0 = (t & 3) * 16;
    int tile = i >> 5;
    int r = i & 31;
    const float* pa = g_pacc + (size_t)(2 * tile) * BI * OUTF + r * OUTF + f0;
    const float* pb = pa + BI * OUTF;
    float l = g_pl[(size_t)(2 * tile) * BI + r] + g_pl[(size_t)(2 * tile + 1) * BI + r];
    float inv = 1.f / l;
#pragma unroll
    for (int c4 = 0; c4 < 4; c4++) {
        float4 a4 = *(const float4*)(pa + c4 * 4);
        float4 b4 = *(const float4*)(pb + c4 * 4);
        float4 o;
        float v;
        v = (a4.x + b4.x) * inv; o.x = (v > 0.f) ? v : expm1f(v);
        v = (a4.y + b4.y) * inv; o.y = (v > 0.f) ? v : expm1f(v);
        v = (a4.z + b4.z) * inv; o.z = (v > 0.f) ? v : expm1f(v);
        v = (a4.w + b4.w) * inv; o.w = (v > 0.f) ? v : expm1f(v);
        *(float4*)(out + (size_t)i * OUTF + f0 + c4 * 4) = o;
    }
}

// ---------------------------------------------------------------------------
extern "C" void kernel_launch(void* const* d_in, const int* in_sizes, int n_in,
                              void* d_out, int out_size) {
    const float* geo  = (const float*)d_in[0];
    const float* sem  = (const float*)d_in[1];
    const float* feat = (const float*)d_in[2];
    const float* W    = (const float*)d_in[3];
    const float* avec = (const float*)d_in[4];
    float* out = (float*)d_out;

    k_h<<<Nn / 16, 256>>>(feat, W, avec);

    cudaFuncSetAttribute(k_main, cudaFuncAttributeMaxDynamicSharedMemorySize, SMEM_BYTES);
    k_main<<<(Nn / BI) * JS, TPB, SMEM_BYTES>>>(geo, sem);

    k_fin<<<Nn / 64, 256>>>(out);
}

// round 13
// speedup vs baseline: 2.1539x; 2.1539x over previous
#include <cuda_runtime.h>
#include <math.h>
#include <stdint.h>

#define Nn 8192
#define IN_FEAT 128
#define OUTF 64
#define LALPHA 0.2f
#define NEG_BIG (-9e15f)

#define BI 32              // rows per tile
#define BJ 64              // j-chunk
#define JS 2               // j-split CTAs per tile
#define NCH ((Nn/JS)/BJ)   // 64 chunks per CTA
#define TPB 256
#define HST 72             // hs stride; 72 % 32 == 8 -> B-frag LDS conflict-free
#define PST 68             // ps stride; 68 % 32 == 4 -> A-frag LDS conflict-free
#define SMEM_BYTES ((2*BJ*HST + 2*BI*PST)*4)   // 54272 B -> 3 CTAs/SM

// Scratch (device globals — no allocation allowed)
__device__ float g_htf[Nn*OUTF];               // h pre-rounded to tf32
__device__ float g_si[Nn];
__device__ float g_sj[Nn];
__device__ unsigned g_sjmax_enc;               // order-preserving encoding
__device__ float g_pacc[(Nn/BI)*JS*BI*OUTF];   // partial P@H per split CTA
__device__ float g_pl[(Nn/BI)*JS*BI];          // partial row sums

__device__ __forceinline__ uint32_t f2tf(float x) {
    uint32_t r;
    asm("cvt.rna.tf32.f32 %0, %1;" : "=r"(r) : "f"(x));
    return r;
}
__device__ __forceinline__ unsigned enc_f(float x) {
    unsigned u = __float_as_uint(x);
    return (u & 0x80000000u) ? ~u : (u | 0x80000000u);
}
__device__ __forceinline__ float dec_f(unsigned u) {
    return __uint_as_float((u & 0x80000000u) ? (u & 0x7FFFFFFFu) : ~u);
}
__device__ __forceinline__ void mma_tf32(float* c,
                                         uint32_t a0, uint32_t a1, uint32_t a2, uint32_t a3,
                                         uint32_t b0, uint32_t b1) {
    asm volatile(
        "mma.sync.aligned.m16n8k8.row.col.f32.tf32.tf32.f32 "
        "{%0,%1,%2,%3}, {%4,%5,%6,%7}, {%8,%9}, {%0,%1,%2,%3};"
        : "+f"(c[0]), "+f"(c[1]), "+f"(c[2]), "+f"(c[3])
        : "r"(a0), "r"(a1), "r"(a2), "r"(a3), "r"(b0), "r"(b1));
}

// ---------------------------------------------------------------------------
// K1: h = features @ W.T (stored tf32-rounded), fused s_i/s_j + max(s_j)
// (exact R10 version: 32 rows/CTA, grid 256)
// ---------------------------------------------------------------------------
__global__ void __launch_bounds__(256) k_h(const float* __restrict__ feat,
                                           const float* __restrict__ W,
                                           const float* __restrict__ avec) {
    __shared__ float Wt[IN_FEAT][OUTF];
    __shared__ float sjred[32];
    int t = threadIdx.x;
#pragma unroll
    for (int w = 0; w < 8; w++) {
        int idx = t + 256 * w;
        int f   = idx >> 5;
        int c4  = idx & 31;
        float4 wv = ((const float4*)W)[idx];
        int k = c4 * 4;
        Wt[k + 0][f] = wv.x;
        Wt[k + 1][f] = wv.y;
        Wt[k + 2][f] = wv.z;
        Wt[k + 3][f] = wv.w;
    }
    __syncthreads();

    int il = t >> 3;
    int fo = t & 7;
    int i  = blockIdx.x * 32 + il;
    const float4* fr = (const float4*)(feat + (size_t)i * IN_FEAT);

    float acc[8];
#pragma unroll
    for (int c = 0; c < 8; c++) acc[c] = 0.f;

#pragma unroll
    for (int kk = 0; kk < 32; kk++) {
        float4 fv = fr[kk];
#pragma unroll
        for (int c = 0; c < 4; c++) {
            float fc = (c == 0) ? fv.x : (c == 1) ? fv.y : (c == 2) ? fv.z : fv.w;
            int k = kk * 4 + c;
            float4 w0 = *(const float4*)&Wt[k][fo * 8];
            float4 w1 = *(const float4*)&Wt[k][fo * 8 + 4];
            acc[0] += fc * w0.x; acc[1] += fc * w0.y;
            acc[2] += fc * w0.z; acc[3] += fc * w0.w;
            acc[4] += fc * w1.x; acc[5] += fc * w1.y;
            acc[6] += fc * w1.z; acc[7] += fc * w1.w;
        }
    }
    uint4 o0, o1;
    o0.x = f2tf(acc[0]); o0.y = f2tf(acc[1]); o0.z = f2tf(acc[2]); o0.w = f2tf(acc[3]);
    o1.x = f2tf(acc[4]); o1.y = f2tf(acc[5]); o1.z = f2tf(acc[6]); o1.w = f2tf(acc[7]);
    *(uint4*)(g_htf + (size_t)i * OUTF + fo * 8)     = o0;
    *(uint4*)(g_htf + (size_t)i * OUTF + fo * 8 + 4) = o1;

    float sx = 0.f, sy = 0.f;
#pragma unroll
    for (int c = 0; c < 8; c++) {
        sx += acc[c] * avec[fo * 8 + c];
        sy += acc[c] * avec[OUTF + fo * 8 + c];
    }
#pragma unroll
    for (int o = 4; o > 0; o >>= 1) {
        sx += __shfl_down_sync(0xffffffffu, sx, o, 8);
        sy += __shfl_down_sync(0xffffffffu, sy, o, 8);
    }
    if (fo == 0) {
        g_si[i] = sx;
        g_sj[i] = sy;
        sjred[il] = sy;
    }
    __syncthreads();
    if (t == 0) {
        float m = sjred[0];
#pragma unroll
        for (int c = 1; c < 32; c++) m = fmaxf(m, sjred[c]);
        atomicMax(&g_sjmax_enc, enc_f(m));   // idempotent across replays
    }
}

// ---------------------------------------------------------------------------
// K2: R10 body; ps double-buffered via POINTER ARITHMETIC (no indexed arrays),
//     ONE sync per chunk. 54.3 KB smem, 3 CTAs/SM, grid 512.
// ---------------------------------------------------------------------------
__global__ void __launch_bounds__(TPB, 3) k_main(const float* __restrict__ geo,
                                                 const float* __restrict__ sem) {
    extern __shared__ float smem[];

    int t     = threadIdx.x;
    int bid   = blockIdx.x;
    int tile  = bid >> 1;
    int half  = bid & 1;
    int i0    = tile * BI;
    int jbase = half * (Nn / JS);
    int lane  = t & 31;
    int warp  = t >> 5;

    // ---- score mapping: 8 threads/row ----
    int r = t >> 3;
    int q = t & 7;
    float si_r  = g_si[i0 + r];
    float m_r   = fmaxf(0.f, 2.f * (si_r + dec_f(g_sjmax_enc)));
    float l_acc = 0.f;
    const float4* gbase = (const float4*)(geo + (size_t)(i0 + r) * Nn + jbase);
    const float4* sbase = (const float4*)(sem + (size_t)(i0 + r) * Nn + jbase);
    const float4* sjb   = (const float4*)(g_sj + jbase);

    // ---- staging mapping ----
    int jr = t >> 4, f4 = t & 15;

    // ---- gemm mapping: 8 warps = 2(m) x 4(n), warp tile m16 x n16 ----
    int wm = warp & 1, wn = warp >> 1;
    int m0 = wm * 16, n0 = wn * 16;
    int ar = lane >> 2, ac = lane & 3;
    int bk = lane & 3,  bn = lane >> 2;

    float acc[2][4];
#pragma unroll
    for (int a = 0; a < 2; a++)
#pragma unroll
        for (int b = 0; b < 4; b++) acc[a][b] = 0.f;

    // prefetch adjacency chunk 0
    float4 gv[2], sv[2];
#pragma unroll
    for (int kk = 0; kk < 2; kk++) {
        gv[kk] = __ldcs(&gbase[q + 8 * kk]);
        sv[kk] = __ldcs(&sbase[q + 8 * kk]);
    }

    int buf = 0;
    for (int ci = 0; ci < NCH; ci++, buf ^= 1) {
        // buffer bases via arithmetic select (register SEL, never local mem)
        float* hs = smem + buf * (BJ * HST);
        float* ps = smem + 2 * (BJ * HST) + buf * (BI * PST);

        // ---- stage h chunk into hs[buf] ----
        int jrow = jbase + ci * BJ;
#pragma unroll
        for (int it = 0; it < 4; it++) {
            int j = jr + 16 * it;
            float4 hv = *(const float4*)(g_htf + (size_t)(jrow + j) * OUTF + f4 * 4);
            *(float4*)(hs + j * HST + f4 * 4) = hv;
        }

        // ---- scores -> ps[buf] ----
        int cb4 = ci * (BJ / 4);
#pragma unroll
        for (int kk = 0; kk < 2; kk++) {
            int f4i = q + 8 * kk;
            int j0l = f4i * 4;
            float4 g4 = gv[kk], s4 = sv[kk];
            float4 sj4 = __ldg(&sjb[cb4 + f4i]);
            uint4 po;
            uint32_t* pd = (uint32_t*)&po;
#pragma unroll
            for (int c = 0; c < 4; c++) {
                float g = (c == 0) ? g4.x : (c == 1) ? g4.y : (c == 2) ? g4.z : g4.w;
                float s = (c == 0) ? s4.x : (c == 1) ? s4.y : (c == 2) ? s4.z : s4.w;
                float sj = (c == 0) ? sj4.x : (c == 1) ? sj4.y : (c == 2) ? sj4.z : sj4.w;
                float cmb = g + s;
                float x = si_r + sj;
                x = (x > 0.f) ? x : LALPHA * x;
                float val = (cmb > 0.f) ? x * cmb : NEG_BIG;
                float p = __expf(val - m_r);
                l_acc += p;
                pd[c] = f2tf(p);
            }
            *(uint4*)(ps + r * PST + j0l) = po;
        }

        // ---- prefetch next adjacency chunk ----
        int cn4 = (ci + 1 < NCH) ? (ci + 1) * (BJ / 4) : 0;
#pragma unroll
        for (int kk = 0; kk < 2; kk++) {
            gv[kk] = __ldcs(&gbase[cn4 + q + 8 * kk]);
            sv[kk] = __ldcs(&sbase[cn4 + q + 8 * kk]);
        }

        __syncthreads();   // writes(ci) visible; also orders re-write of this
                           // buffer at ci+2 behind GEMM(ci) of every warp

        // ---- tensor-core GEMM: acc += P[32,64] @ H[64,64] ----
        const float* psA = ps + (m0 + ar) * PST + ac;
        const float* hsB = hs + bk * HST + n0 + bn;
#pragma unroll
        for (int ks = 0; ks < 8; ks++) {
            int k0 = ks * 8;
            uint32_t a0 = __float_as_uint(psA[k0]);
            uint32_t a1 = __float_as_uint(psA[8 * PST + k0]);
            uint32_t a2 = __float_as_uint(psA[k0 + 4]);
            uint32_t a3 = __float_as_uint(psA[8 * PST + k0 + 4]);
#pragma unroll
            for (int nt = 0; nt < 2; nt++) {
                uint32_t b0 = __float_as_uint(hsB[k0 * HST + nt * 8]);
                uint32_t b1 = __float_as_uint(hsB[(k0 + 4) * HST + nt * 8]);
                mma_tf32(acc[nt], a0, a1, a2, a3, b0, b1);
            }
        }
    }

    // ---- partial l: reduce across the 8 threads of each row ----
#pragma unroll
    for (int o = 4; o > 0; o >>= 1)
        l_acc += __shfl_down_sync(0xffffffffu, l_acc, o, 8);
    if (q == 0) g_pl[(size_t)bid * BI + r] = l_acc;

    // ---- partial acc -> global (unnormalized; exact since m_r is global) ----
    float* pout = g_pacc + (size_t)bid * BI * OUTF;
    int row0 = m0 + (lane >> 2);
    int col0 = 2 * (lane & 3);
#pragma unroll
    for (int nt = 0; nt < 2; nt++) {
        int col = n0 + nt * 8 + col0;
        *(float2*)(pout + row0 * OUTF + col)       = make_float2(acc[nt][0], acc[nt][1]);
        *(float2*)(pout + (row0 + 8) * OUTF + col) = make_float2(acc[nt][2], acc[nt][3]);
    }
}

// ---------------------------------------------------------------------------
// K3: combine j-split partials, normalize, ELU
// ---------------------------------------------------------------------------
__global__ void __launch_bounds__(256) k_fin(float* __restrict__ out) {
    int t = threadIdx.x;
    int i = blockIdx.x * 64 + (t >> 2);
    int f0 = (t & 3) * 16;
    int tile = i >> 5;
    int r = i & 31;
    const float* pa = g_pacc + (size_t)(2 * tile) * BI * OUTF + r * OUTF + f0;
    const float* pb = pa + BI * OUTF;
    float l = g_pl[(size_t)(2 * tile) * BI + r] + g_pl[(size_t)(2 * tile + 1) * BI + r];
    float inv = 1.f / l;
#pragma unroll
    for (int c4 = 0; c4 < 4; c4++) {
        float4 a4 = *(const float4*)(pa + c4 * 4);
        float4 b4 = *(const float4*)(pb + c4 * 4);
        float4 o;
        float v;
        v = (a4.x + b4.x) * inv; o.x = (v > 0.f) ? v : expm1f(v);
        v = (a4.y + b4.y) * inv; o.y = (v > 0.f) ? v : expm1f(v);
        v = (a4.z + b4.z) * inv; o.z = (v > 0.f) ? v : expm1f(v);
        v = (a4.w + b4.w) * inv; o.w = (v > 0.f) ? v : expm1f(v);
        *(float4*)(out + (size_t)i * OUTF + f0 + c4 * 4) = o;
    }
}

// ---------------------------------------------------------------------------
extern "C" void kernel_launch(void* const* d_in, const int* in_sizes, int n_in,
                              void* d_out, int out_size) {
    const float* geo  = (const float*)d_in[0];
    const float* sem  = (const float*)d_in[1];
    const float* feat = (const float*)d_in[2];
    const float* W    = (const float*)d_in[3];
    const float* avec = (const float*)d_in[4];
    float* out = (float*)d_out;

    k_h<<<Nn / 32, 256>>>(feat, W, avec);

    cudaFuncSetAttribute(k_main, cudaFuncAttributeMaxDynamicSharedMemorySize, SMEM_BYTES);
    k_main<<<(Nn / BI) * JS, TPB, SMEM_BYTES>>>(geo, sem);

    k_fin<<<Nn / 64, 256>>>(out);
}

// round 15
// speedup vs baseline: 2.4092x; 1.1186x over previous
#include <cuda_runtime.h>
#include <math.h>
#include <stdint.h>

#define Nn 8192
#define IN_FEAT 128
#define OUTF 64
#define LALPHA 0.2f
#define NEG_BIG (-9e15f)

#define BI 32              // rows per tile
#define BJ 64              // j-chunk
#define JS 8               // j-split CTAs per tile -> grid 2048, 92% slot util
#define NCH ((Nn/JS)/BJ)   // 16 chunks per CTA
#define TPB 256
#define HST 72             // hs stride; 72 % 32 == 8 -> B-frag LDS conflict-free
#define PST 68             // ps stride; 68 % 32 == 4 -> A-frag LDS conflict-free
#define SMEM_BYTES ((2*BJ*HST + 2*BI*PST)*4)   // 54272 B -> 3 CTAs/SM

// Scratch (device globals — no allocation allowed)
__device__ float g_htf[Nn*OUTF];               // h pre-rounded to tf32
__device__ float g_si[Nn];
__device__ float g_sj[Nn];
__device__ unsigned g_sjmax_enc;               // order-preserving encoding
__device__ float g_pacc[(Nn/BI)*JS*BI*OUTF];   // partial P@H per split CTA
__device__ float g_pl[(Nn/BI)*JS*BI];          // partial row sums

__device__ __forceinline__ uint32_t f2tf(float x) {
    uint32_t r;
    asm("cvt.rna.tf32.f32 %0, %1;" : "=r"(r) : "f"(x));
    return r;
}
__device__ __forceinline__ unsigned enc_f(float x) {
    unsigned u = __float_as_uint(x);
    return (u & 0x80000000u) ? ~u : (u | 0x80000000u);
}
__device__ __forceinline__ float dec_f(unsigned u) {
    return __uint_as_float((u & 0x80000000u) ? (u & 0x7FFFFFFFu) : ~u);
}
__device__ __forceinline__ void mma_tf32(float* c,
                                         uint32_t a0, uint32_t a1, uint32_t a2, uint32_t a3,
                                         uint32_t b0, uint32_t b1) {
    asm volatile(
        "mma.sync.aligned.m16n8k8.row.col.f32.tf32.tf32.f32 "
        "{%0,%1,%2,%3}, {%4,%5,%6,%7}, {%8,%9}, {%0,%1,%2,%3};"
        : "+f"(c[0]), "+f"(c[1]), "+f"(c[2]), "+f"(c[3])
        : "r"(a0), "r"(a1), "r"(a2), "r"(a3), "r"(b0), "r"(b1));
}

// ---------------------------------------------------------------------------
// K1: h = features @ W.T (stored tf32-rounded), fused s_i/s_j + max(s_j)
// (unchanged R10 version)
// ---------------------------------------------------------------------------
__global__ void __launch_bounds__(256) k_h(const float* __restrict__ feat,
                                           const float* __restrict__ W,
                                           const float* __restrict__ avec) {
    __shared__ float Wt[IN_FEAT][OUTF];
    __shared__ float sjred[32];
    int t = threadIdx.x;
#pragma unroll
    for (int w = 0; w < 8; w++) {
        int idx = t + 256 * w;
        int f   = idx >> 5;
        int c4  = idx & 31;
        float4 wv = ((const float4*)W)[idx];
        int k = c4 * 4;
        Wt[k + 0][f] = wv.x;
        Wt[k + 1][f] = wv.y;
        Wt[k + 2][f] = wv.z;
        Wt[k + 3][f] = wv.w;
    }
    __syncthreads();

    int il = t >> 3;
    int fo = t & 7;
    int i  = blockIdx.x * 32 + il;
    const float4* fr = (const float4*)(feat + (size_t)i * IN_FEAT);

    float acc[8];
#pragma unroll
    for (int c = 0; c < 8; c++) acc[c] = 0.f;

#pragma unroll
    for (int kk = 0; kk < 32; kk++) {
        float4 fv = fr[kk];
#pragma unroll
        for (int c = 0; c < 4; c++) {
            float fc = (c == 0) ? fv.x : (c == 1) ? fv.y : (c == 2) ? fv.z : fv.w;
            int k = kk * 4 + c;
            float4 w0 = *(const float4*)&Wt[k][fo * 8];
            float4 w1 = *(const float4*)&Wt[k][fo * 8 + 4];
            acc[0] += fc * w0.x; acc[1] += fc * w0.y;
            acc[2] += fc * w0.z; acc[3] += fc * w0.w;
            acc[4] += fc * w1.x; acc[5] += fc * w1.y;
            acc[6] += fc * w1.z; acc[7] += fc * w1.w;
        }
    }
    uint4 o0, o1;
    o0.x = f2tf(acc[0]); o0.y = f2tf(acc[1]); o0.z = f2tf(acc[2]); o0.w = f2tf(acc[3]);
    o1.x = f2tf(acc[4]); o1.y = f2tf(acc[5]); o1.z = f2tf(acc[6]); o1.w = f2tf(acc[7]);
    *(uint4*)(g_htf + (size_t)i * OUTF + fo * 8)     = o0;
    *(uint4*)(g_htf + (size_t)i * OUTF + fo * 8 + 4) = o1;

    float sx = 0.f, sy = 0.f;
#pragma unroll
    for (int c = 0; c < 8; c++) {
        sx += acc[c] * avec[fo * 8 + c];
        sy += acc[c] * avec[OUTF + fo * 8 + c];
    }
#pragma unroll
    for (int o = 4; o > 0; o >>= 1) {
        sx += __shfl_down_sync(0xffffffffu, sx, o, 8);
        sy += __shfl_down_sync(0xffffffffu, sy, o, 8);
    }
    if (fo == 0) {
        g_si[i] = sx;
        g_sj[i] = sy;
        sjred[il] = sy;
    }
    __syncthreads();
    if (t == 0) {
        float m = sjred[0];
#pragma unroll
        for (int c = 1; c < 32; c++) m = fmaxf(m, sjred[c]);
        atomicMax(&g_sjmax_enc, enc_f(m));   // idempotent across replays
    }
}

// ---------------------------------------------------------------------------
// K2: R13 body verbatim; only the work decomposition changes (JS=8).
// Grid 2048 CTAs, 3 CTAs/SM, 16 chunks each.
// ---------------------------------------------------------------------------
__global__ void __launch_bounds__(TPB, 3) k_main(const float* __restrict__ geo,
                                                 const float* __restrict__ sem) {
    extern __shared__ float smem[];

    int t     = threadIdx.x;
    int bid   = blockIdx.x;
    int tile  = bid >> 3;
    int part  = bid & 7;
    int i0    = tile * BI;
    int jbase = part * (Nn / JS);
    int lane  = t & 31;
    int warp  = t >> 5;

    // ---- score mapping: 8 threads/row ----
    int r = t >> 3;
    int q = t & 7;
    float si_r  = g_si[i0 + r];
    float m_r   = fmaxf(0.f, 2.f * (si_r + dec_f(g_sjmax_enc)));
    float l_acc = 0.f;
    const float4* gbase = (const float4*)(geo + (size_t)(i0 + r) * Nn + jbase);
    const float4* sbase = (const float4*)(sem + (size_t)(i0 + r) * Nn + jbase);
    const float4* sjb   = (const float4*)(g_sj + jbase);

    // ---- staging mapping ----
    int jr = t >> 4, f4 = t & 15;

    // ---- gemm mapping: 8 warps = 2(m) x 4(n), warp tile m16 x n16 ----
    int wm = warp & 1, wn = warp >> 1;
    int m0 = wm * 16, n0 = wn * 16;
    int ar = lane >> 2, ac = lane & 3;
    int bk = lane & 3,  bn = lane >> 2;

    float acc[2][4];
#pragma unroll
    for (int a = 0; a < 2; a++)
#pragma unroll
        for (int b = 0; b < 4; b++) acc[a][b] = 0.f;

    // prefetch adjacency chunk 0
    float4 gv[2], sv[2];
#pragma unroll
    for (int kk = 0; kk < 2; kk++) {
        gv[kk] = __ldcs(&gbase[q + 8 * kk]);
        sv[kk] = __ldcs(&sbase[q + 8 * kk]);
    }

    int buf = 0;
    for (int ci = 0; ci < NCH; ci++, buf ^= 1) {
        // buffer bases via arithmetic select (register SEL, never local mem)
        float* hs = smem + buf * (BJ * HST);
        float* ps = smem + 2 * (BJ * HST) + buf * (BI * PST);

        // ---- stage h chunk into hs[buf] ----
        int jrow = jbase + ci * BJ;
#pragma unroll
        for (int it = 0; it < 4; it++) {
            int j = jr + 16 * it;
            float4 hv = *(const float4*)(g_htf + (size_t)(jrow + j) * OUTF + f4 * 4);
            *(float4*)(hs + j * HST + f4 * 4) = hv;
        }

        // ---- scores -> ps[buf] ----
        int cb4 = ci * (BJ / 4);
#pragma unroll
        for (int kk = 0; kk < 2; kk++) {
            int f4i = q + 8 * kk;
            int j0l = f4i * 4;
            float4 g4 = gv[kk], s4 = sv[kk];
            float4 sj4 = __ldg(&sjb[cb4 + f4i]);
            uint4 po;
            uint32_t* pd = (uint32_t*)&po;
#pragma unroll
            for (int c = 0; c < 4; c++) {
                float g = (c == 0) ? g4.x : (c == 1) ? g4.y : (c == 2) ? g4.z : g4.w;
                float s = (c == 0) ? s4.x : (c == 1) ? s4.y : (c == 2) ? s4.z : s4.w;
                float sj = (c == 0) ? sj4.x : (c == 1) ? sj4.y : (c == 2) ? sj4.z : sj4.w;
                float cmb = g + s;
                float x = si_r + sj;
                x = (x > 0.f) ? x : LALPHA * x;
                float val = (cmb > 0.f) ? x * cmb : NEG_BIG;
                float p = __expf(val - m_r);
                l_acc += p;
                pd[c] = f2tf(p);
            }
            *(uint4*)(ps + r * PST + j0l) = po;
        }

        // ---- prefetch next adjacency chunk ----
        int cn4 = (ci + 1 < NCH) ? (ci + 1) * (BJ / 4) : 0;
#pragma unroll
        for (int kk = 0; kk < 2; kk++) {
            gv[kk] = __ldcs(&gbase[cn4 + q + 8 * kk]);
            sv[kk] = __ldcs(&sbase[cn4 + q + 8 * kk]);
        }

        __syncthreads();   // writes(ci) visible; orders buffer reuse at ci+2

        // ---- tensor-core GEMM: acc += P[32,64] @ H[64,64] ----
        const float* psA = ps + (m0 + ar) * PST + ac;
        const float* hsB = hs + bk * HST + n0 + bn;
#pragma unroll
        for (int ks = 0; ks < 8; ks++) {
            int k0 = ks * 8;
            uint32_t a0 = __float_as_uint(psA[k0]);
            uint32_t a1 = __float_as_uint(psA[8 * PST + k0]);
            uint32_t a2 = __float_as_uint(psA[k0 + 4]);
            uint32_t a3 = __float_as_uint(psA[8 * PST + k0 + 4]);
#pragma unroll
            for (int nt = 0; nt < 2; nt++) {
                uint32_t b0 = __float_as_uint(hsB[k0 * HST + nt * 8]);
                uint32_t b1 = __float_as_uint(hsB[(k0 + 4) * HST + nt * 8]);
                mma_tf32(acc[nt], a0, a1, a2, a3, b0, b1);
            }
        }
    }

    // ---- partial l: reduce across the 8 threads of each row ----
#pragma unroll
    for (int o = 4; o > 0; o >>= 1)
        l_acc += __shfl_down_sync(0xffffffffu, l_acc, o, 8);
    if (q == 0) g_pl[(size_t)bid * BI + r] = l_acc;

    // ---- partial acc -> global (unnormalized; exact since m_r is global) ----
    float* pout = g_pacc + (size_t)bid * BI * OUTF;
    int row0 = m0 + (lane >> 2);
    int col0 = 2 * (lane & 3);
#pragma unroll
    for (int nt = 0; nt < 2; nt++) {
        int col = n0 + nt * 8 + col0;
        *(float2*)(pout + row0 * OUTF + col)       = make_float2(acc[nt][0], acc[nt][1]);
        *(float2*)(pout + (row0 + 8) * OUTF + col) = make_float2(acc[nt][2], acc[nt][3]);
    }
}

// ---------------------------------------------------------------------------
// K3: combine JS=8 partials, normalize, ELU
// ---------------------------------------------------------------------------
__global__ void __launch_bounds__(256) k_fin(float* __restrict__ out) {
    int t = threadIdx.x;
    int i = blockIdx.x * 64 + (t >> 2);
    int f0 = (t & 3) * 16;
    int tile = i >> 5;
    int r = i & 31;
    const float* pa = g_pacc + (size_t)tile * JS * BI * OUTF + r * OUTF + f0;

    float l = 0.f;
#pragma unroll
    for (int s = 0; s < JS; s++)
        l += g_pl[((size_t)tile * JS + s) * BI + r];
    float inv = 1.f / l;

#pragma unroll
    for (int c4 = 0; c4 < 4; c4++) {
        float4 a4 = make_float4(0.f, 0.f, 0.f, 0.f);
#pragma unroll
        for (int s = 0; s < JS; s++) {
            float4 v = *(const float4*)(pa + (size_t)s * BI * OUTF + c4 * 4);
            a4.x += v.x; a4.y += v.y; a4.z += v.z; a4.w += v.w;
        }
        float4 o;
        float v;
        v = a4.x * inv; o.x = (v > 0.f) ? v : expm1f(v);
        v = a4.y * inv; o.y = (v > 0.f) ? v : expm1f(v);
        v = a4.z * inv; o.z = (v > 0.f) ? v : expm1f(v);
        v = a4.w * inv; o.w = (v > 0.f) ? v : expm1f(v);
        *(float4*)(out + (size_t)i * OUTF + f0 + c4 * 4) = o;
    }
}

// ---------------------------------------------------------------------------
extern "C" void kernel_launch(void* const* d_in, const int* in_sizes, int n_in,
                              void* d_out, int out_size) {
    const float* geo  = (const float*)d_in[0];
    const float* sem  = (const float*)d_in[1];
    const float* feat = (const float*)d_in[2];
    const float* W    = (const float*)d_in[3];
    const float* avec = (const float*)d_in[4];
    float* out = (float*)d_out;

    k_h<<<Nn / 32, 256>>>(feat, W, avec);

    cudaFuncSetAttribute(k_main, cudaFuncAttributeMaxDynamicSharedMemorySize, SMEM_BYTES);
    k_main<<<(Nn / BI) * JS, TPB, SMEM_BYTES>>>(geo, sem);

    k_fin<<<Nn / 64, 256>>>(out);
}